// round 5
// baseline (speedup 1.0000x reference)
#include <cuda_runtime.h>
#include <climits>

// ---- problem-size caps (ref: N=100000, E=1600000, G=512, F=128) ----
#define MAXN 131072
#define MAXG 4096
#define MAXB 1024   // max blocks participating in the grid barrier

// scratch (no cudaMalloc allowed)
__device__ float  g_dot[MAXN];   // x@W per node
__device__ int    g_cnt[MAXN];   // in-degree (deg = cnt+1)
__device__ float2 g_ut[MAXN];    // .x = gather source u, .y = accumulator t
__device__ float  g_dinv[MAXN];  // 1/deg
__device__ float  g_dis[MAXN];   // deg^-1/2
__device__ float  g_sum[MAXG];
__device__ int    g_gcnt[MAXG];

// software grid barrier state (reset to 0 at end of every launch)
__device__ volatile int g_arr[MAXB];
__device__ volatile int g_gen;

// distributed-slot grid barrier: each block posts `phase` to its own slot;
// block 0 polls all slots then publishes to g_gen; others spin on g_gen.
__device__ __forceinline__ void gsync(int phase, int nb) {
    __syncthreads();
    if (blockIdx.x == 0) {
        if (threadIdx.x == 0) __threadfence();
        __syncthreads();
        for (int s = 1 + threadIdx.x; s < nb; s += blockDim.x)
            while (g_arr[s] < phase) { }
        __syncthreads();
        if (threadIdx.x == 0) { __threadfence(); g_gen = phase; }
    } else if (threadIdx.x == 0) {
        __threadfence();
        g_arr[blockIdx.x] = phase;
        while (g_gen < phase) { }
        __threadfence();
    }
    __syncthreads();
}

// end-of-launch reset so the next graph replay starts clean.
__device__ __forceinline__ void greset(int nb) {
    __syncthreads();
    if (threadIdx.x == 0) {
        if (blockIdx.x != 0) {
            g_arr[blockIdx.x] = 0;
        } else {
            for (int s = 1; s < nb; s++) while (g_arr[s] != 0) { }
            __threadfence();
            g_gen = 0;
        }
    }
}

__global__ void __launch_bounds__(1024, 2)
sgconv_fused(const float* __restrict__ x, const float* __restrict__ W,
             const float* __restrict__ bias,
             const int* __restrict__ row, const int* __restrict__ col,
             const int* __restrict__ batch,
             float* __restrict__ out,
             int n, int F, int E, int G, int nb) {
    const int tid    = blockIdx.x * blockDim.x + threadIdx.x;
    const int nth    = gridDim.x * blockDim.x;
    const int lane   = threadIdx.x & 31;
    const int warp   = tid >> 5;
    const int nwarps = nth >> 5;
    const bool vec4  = ((E & 3) == 0);
    const int  E4    = E >> 2;
    int phase = 0;

    // ---- PH_A: zero scratch ----
    for (int i = tid; i < n; i += nth) g_cnt[i] = 0;
    for (int i = tid; i < G; i += nth) { g_sum[i] = 0.0f; g_gcnt[i] = 0; }
    gsync(++phase, nb);

    // ---- PH_B: degree count + per-graph counts + GEMV ----
    if (vec4) {
        for (int q = tid; q < E4; q += nth) {
            int4 c = reinterpret_cast<const int4*>(col)[q];
            atomicAdd(&g_cnt[c.x], 1); atomicAdd(&g_cnt[c.y], 1);
            atomicAdd(&g_cnt[c.z], 1); atomicAdd(&g_cnt[c.w], 1);
        }
    } else {
        for (int e = tid; e < E; e += nth) atomicAdd(&g_cnt[col[e]], 1);
    }

    // per-graph node counts (batch is sorted -> warp aggregation)
    for (int base = warp * 32; base < n; base += nwarps * 32) {
        int i = base + lane;
        int b = (i < n) ? batch[i] : -1;
        unsigned peers = __match_any_sync(0xffffffffu, b);
        if (b >= 0 && (int)(__ffs(peers) - 1) == lane)
            atomicAdd(&g_gcnt[b], __popc(peers));
    }

    // GEMV: dot[i] = x[i,:] @ W, one warp per node
    if (F == 128) {
        float4 wv = *reinterpret_cast<const float4*>(W + lane * 4);
        for (int node = warp; node < n; node += nwarps) {
            float4 xv = *reinterpret_cast<const float4*>(x + (size_t)node * 128 + lane * 4);
            float acc = xv.x * wv.x + xv.y * wv.y + xv.z * wv.z + xv.w * wv.w;
            #pragma unroll
            for (int o = 16; o; o >>= 1) acc += __shfl_xor_sync(0xffffffffu, acc, o);
            if (lane == 0) g_dot[node] = acc;
        }
    } else {
        for (int node = warp; node < n; node += nwarps) {
            const float* xr = x + (size_t)node * F;
            float acc = 0.0f;
            for (int j = lane; j < F; j += 32) acc += xr[j] * W[j];
            #pragma unroll
            for (int o = 16; o; o >>= 1) acc += __shfl_xor_sync(0xffffffffu, acc, o);
            if (lane == 0) g_dot[node] = acc;
        }
    }
    gsync(++phase, nb);

    // ---- PH_C: diagonal scalings; u0 = t0 = dis * dot ----
    for (int i = tid; i < n; i += nth) {
        float deg  = (float)(g_cnt[i] + 1);   // +1 self-loop
        float dinv = __frcp_rn(deg);
        float dis  = rsqrtf(deg);
        g_dinv[i] = dinv;
        g_dis[i]  = dis;
        float u = dis * g_dot[i];
        g_ut[i] = make_float2(u, u);          // u = gather src, t = self-loop term
    }
    gsync(++phase, nb);

    // ---- 3 hops: t[col] += u[row]; between hops t *= dinv, u = t ----
    #pragma unroll
    for (int hop = 0; hop < 3; hop++) {
        if (vec4) {
            for (int q = tid; q < E4; q += nth) {
                int4 r = reinterpret_cast<const int4*>(row)[q];
                int4 c = reinterpret_cast<const int4*>(col)[q];
                float v0 = __ldg(&g_ut[r.x].x);
                float v1 = __ldg(&g_ut[r.y].x);
                float v2 = __ldg(&g_ut[r.z].x);
                float v3 = __ldg(&g_ut[r.w].x);
                atomicAdd(&g_ut[c.x].y, v0);
                atomicAdd(&g_ut[c.y].y, v1);
                atomicAdd(&g_ut[c.z].y, v2);
                atomicAdd(&g_ut[c.w].y, v3);
            }
        } else {
            for (int e = tid; e < E; e += nth)
                atomicAdd(&g_ut[col[e]].y, __ldg(&g_ut[row[e]].x));
        }
        gsync(++phase, nb);
        if (hop < 2) {
            for (int i = tid; i < n; i += nth) {
                float v = g_ut[i].y * g_dinv[i];
                g_ut[i] = make_float2(v, v);
            }
            gsync(++phase, nb);
        }
    }

    // ---- per-graph sums: segmented warp reduction (batch sorted) ----
    for (int base = warp * 32; base < n; base += nwarps * 32) {
        int i = base + lane;
        float v = (i < n) ? g_dis[i] * g_ut[i].y : 0.0f;
        int   b = (i < n) ? batch[i] : INT_MAX;
        #pragma unroll
        for (int o = 1; o < 32; o <<= 1) {
            float vv = __shfl_down_sync(0xffffffffu, v, o);
            int   bb = __shfl_down_sync(0xffffffffu, b, o);
            if (lane + o < 32 && bb == b) v += vv;
        }
        int bp = __shfl_up_sync(0xffffffffu, b, 1);
        if (i < n && (lane == 0 || bp != b)) atomicAdd(&g_sum[b], v);
    }
    gsync(++phase, nb);

    // ---- final: block 0 writes output ----
    if (blockIdx.x == 0) {
        for (int g = threadIdx.x; g < G; g += blockDim.x) {
            int c = g_gcnt[g];
            out[g] = (c > 0) ? (g_sum[g] / (float)c + bias[0]) : 0.0f;
        }
    }

    greset(nb);
}

extern "C" void kernel_launch(void* const* d_in, const int* in_sizes, int n_in,
                              void* d_out, int out_size) {
    const float* x     = (const float*)d_in[0];   // [N, F]
    const float* W     = (const float*)d_in[1];   // [F, 1]
    const float* b     = (const float*)d_in[2];   // [1]
    const int*   ei    = (const int*)d_in[3];     // [2, E]
    const int*   batch = (const int*)d_in[4];     // [N]

    int F = in_sizes[1];
    int n = in_sizes[4];
    int E = in_sizes[3] / 2;
    int G = out_size;

    const int* row = ei;       // edge_index[0]
    const int* col = ei + E;   // edge_index[1]

    int dev = 0;
    cudaGetDevice(&dev);
    int nsm = 148;
    cudaDeviceGetAttribute(&nsm, cudaDevAttrMultiProcessorCount, dev);
    int nb = 2 * nsm;                    // 2 co-resident blocks per SM
    if (nb > MAXB) nb = MAXB;

    sgconv_fused<<<nb, 1024>>>(x, W, b, row, col, batch, (float*)d_out,
                               n, F, E, G, nb);
}

// round 6
// speedup vs baseline: 2.4099x; 2.4099x over previous
#include <cuda_runtime.h>

// ---- problem-size caps (ref: N=100000, E=1600000, G=512, F=128) ----
#define MAXN 131072
#define NSM  148

// scratch (no cudaMalloc allowed)
__device__ float g_dot[MAXN];   // x@W per node
__device__ int   g_cnt[MAXN];   // in-degree count (deg = cnt + 1)
__device__ float g_u[MAXN];     // gather source of current hop
__device__ float g_t[MAXN];     // accumulator of current hop
__device__ float g_dinv[MAXN];  // 1/deg
__device__ float g_dis[MAXN];   // deg^-1/2

#if defined(__CUDA_ARCH__) && (__CUDA_ARCH__ >= 900)
#define GRID_DEP_SYNC() cudaGridDependencySynchronize()
#else
#define GRID_DEP_SYNC()
#endif

// ---------------------------------------------------------------------------
// Fused preamble, block-range specialized:
//   blocks [0, nGemv):      dot[i] = x[i,:] @ W      (DRAM streaming)
//   blocks [nGemv, grid):   cnt[col[e]] += 1         (random atomics)
// ---------------------------------------------------------------------------
__global__ void k_pre(const float* __restrict__ x, const float* __restrict__ W,
                      const int* __restrict__ col,
                      int n, int F, int E, int nGemv) {
    int lane = threadIdx.x & 31;
    if (blockIdx.x < nGemv) {
        int warp   = (blockIdx.x * blockDim.x + threadIdx.x) >> 5;
        int nwarps = (nGemv * blockDim.x) >> 5;
        if (F == 128) {
            float4 wv = *reinterpret_cast<const float4*>(W + lane * 4);
            for (int node = warp; node < n; node += nwarps) {
                float4 xv = *reinterpret_cast<const float4*>(x + (size_t)node * 128 + lane * 4);
                float acc = xv.x * wv.x + xv.y * wv.y + xv.z * wv.z + xv.w * wv.w;
                #pragma unroll
                for (int o = 16; o; o >>= 1) acc += __shfl_xor_sync(0xffffffffu, acc, o);
                if (lane == 0) g_dot[node] = acc;
            }
        } else {
            for (int node = warp; node < n; node += nwarps) {
                const float* xr = x + (size_t)node * F;
                float acc = 0.0f;
                for (int j = lane; j < F; j += 32) acc += xr[j] * W[j];
                #pragma unroll
                for (int o = 16; o; o >>= 1) acc += __shfl_xor_sync(0xffffffffu, acc, o);
                if (lane == 0) g_dot[node] = acc;
            }
        }
    } else {
        int tid = (blockIdx.x - nGemv) * blockDim.x + threadIdx.x;
        int nth = (gridDim.x - nGemv) * blockDim.x;
        int E4  = E >> 2;
        for (int q = tid; q < E4; q += nth) {
            int4 c = reinterpret_cast<const int4*>(col)[q];
            atomicAdd(&g_cnt[c.x], 1);
            atomicAdd(&g_cnt[c.y], 1);
            atomicAdd(&g_cnt[c.z], 1);
            atomicAdd(&g_cnt[c.w], 1);
        }
        if (tid == 0) for (int e = E4 << 2; e < E; e++) atomicAdd(&g_cnt[col[e]], 1);
    }
}

// u[i] = t[i] = dis[i] * dot[i]; stash dinv, dis
__global__ void k_scale(int n) {
    GRID_DEP_SYNC();
    int i = blockIdx.x * blockDim.x + threadIdx.x;
    if (i < n) {
        float deg  = (float)(g_cnt[i] + 1);   // self-loop
        float dinv = __frcp_rn(deg);
        float dis  = rsqrtf(deg);
        g_dinv[i] = dinv;
        g_dis[i]  = dis;
        float u = dis * g_dot[i];
        g_u[i] = u;
        g_t[i] = u;
    }
}

// t[col[e]] += u[row[e]], single-wave grid-stride, 4 edges per iteration
__global__ void k_scatter(const int* __restrict__ row, const int* __restrict__ col, int E) {
    GRID_DEP_SYNC();
    int tid = blockIdx.x * blockDim.x + threadIdx.x;
    int nth = gridDim.x * blockDim.x;
    int E4  = E >> 2;
    for (int q = tid; q < E4; q += nth) {
        int4 r = reinterpret_cast<const int4*>(row)[q];
        int4 c = reinterpret_cast<const int4*>(col)[q];
        float v0 = __ldg(&g_u[r.x]);
        float v1 = __ldg(&g_u[r.y]);
        float v2 = __ldg(&g_u[r.z]);
        float v3 = __ldg(&g_u[r.w]);
        atomicAdd(&g_t[c.x], v0);
        atomicAdd(&g_t[c.y], v1);
        atomicAdd(&g_t[c.z], v2);
        atomicAdd(&g_t[c.w], v3);
    }
    if (tid == 0) for (int e = E4 << 2; e < E; e++) atomicAdd(&g_t[col[e]], g_u[row[e]]);
}

// between hops: t *= 1/deg; u = t
__global__ void k_mid(int n) {
    GRID_DEP_SYNC();
    int i = blockIdx.x * blockDim.x + threadIdx.x;
    if (i < n) {
        float v = g_t[i] * g_dinv[i];
        g_t[i] = v;
        g_u[i] = v;
    }
}

// fused scatter-mean + output: block g owns graph g. batch is sorted, so the
// segment is found by binary search; block-reduce dis*t over it.
__global__ void k_out(const int* __restrict__ batch, const float* __restrict__ bias,
                      float* __restrict__ out, int n) {
    GRID_DEP_SYNC();
    __shared__ int s_lo, s_hi;
    __shared__ float s_part[8];
    int g = blockIdx.x;

    if (threadIdx.x < 2) {
        int target = g + threadIdx.x;        // lower_bound(target)
        int lo = 0, hi = n;
        while (lo < hi) {
            int mid = (lo + hi) >> 1;
            if (batch[mid] < target) lo = mid + 1; else hi = mid;
        }
        if (threadIdx.x == 0) s_lo = lo; else s_hi = lo;
    }
    __syncthreads();

    int lo = s_lo, hi = s_hi;
    float local = 0.0f;
    for (int i = lo + threadIdx.x; i < hi; i += blockDim.x)
        local += g_dis[i] * g_t[i];

    #pragma unroll
    for (int o = 16; o; o >>= 1) local += __shfl_xor_sync(0xffffffffu, local, o);
    int warp = threadIdx.x >> 5;
    if ((threadIdx.x & 31) == 0) s_part[warp] = local;
    __syncthreads();
    if (threadIdx.x == 0) {
        float sum = 0.0f;
        #pragma unroll
        for (int w = 0; w < 8; w++) sum += s_part[w];
        int c = hi - lo;
        out[g] = (c > 0) ? (sum / (float)c + bias[0]) : 0.0f;
    }
}

// ---------------------------------------------------------------------------
extern "C" void kernel_launch(void* const* d_in, const int* in_sizes, int n_in,
                              void* d_out, int out_size) {
    const float* x     = (const float*)d_in[0];   // [N, F]
    const float* W     = (const float*)d_in[1];   // [F, 1]
    const float* b     = (const float*)d_in[2];   // [1]
    const int*   ei    = (const int*)d_in[3];     // [2, E]
    const int*   batch = (const int*)d_in[4];     // [N]

    int F = in_sizes[1];
    int n = in_sizes[4];
    int E = in_sizes[3] / 2;
    int G = out_size;

    const int* row = ei;       // edge_index[0]
    const int* col = ei + E;   // edge_index[1]

    const int TB = 256;
    auto nbk = [](int v, int tb) { return (v + tb - 1) / tb; };

    // zero in-degree counters
    void* p_cnt;
    cudaGetSymbolAddress(&p_cnt, g_cnt);
    cudaMemsetAsync(p_cnt, 0, (size_t)n * sizeof(int));

    // PDL-enabled launch helper
    cudaLaunchAttribute pdlAttr[1];
    pdlAttr[0].id = cudaLaunchAttributeProgrammaticStreamSerialization;
    pdlAttr[0].val.programmaticStreamSerializationAllowed = 1;

    // --- preamble (predecessor is a memset: no PDL) ---
    int nGemv = NSM * 5;                 // 740 DRAM-streaming blocks
    int nDeg  = NSM * 3;                 // 444 random-atomic blocks
    k_pre<<<nGemv + nDeg, TB>>>(x, W, col, n, F, E, nGemv);

    // --- remaining kernels: PDL-chained ---
    {
        cudaLaunchConfig_t cfg = {};
        cfg.blockDim = dim3(TB, 1, 1);
        cfg.attrs = pdlAttr;
        cfg.numAttrs = 1;

        cfg.gridDim = dim3(nbk(n, TB), 1, 1);
        cudaLaunchKernelEx(&cfg, k_scale, n);

        const int scatGrid = NSM * 8;    // single wave @ 2048 thr/SM
        cfg.gridDim = dim3(scatGrid, 1, 1);
        cudaLaunchKernelEx(&cfg, k_scatter, row, col, E);

        cfg.gridDim = dim3(nbk(n, TB), 1, 1);
        cudaLaunchKernelEx(&cfg, k_mid, n);

        cfg.gridDim = dim3(scatGrid, 1, 1);
        cudaLaunchKernelEx(&cfg, k_scatter, row, col, E);

        cfg.gridDim = dim3(nbk(n, TB), 1, 1);
        cudaLaunchKernelEx(&cfg, k_mid, n);

        cfg.gridDim = dim3(scatGrid, 1, 1);
        cudaLaunchKernelEx(&cfg, k_scatter, row, col, E);

        cfg.gridDim = dim3(G, 1, 1);
        cudaLaunchKernelEx(&cfg, k_out, batch, b, (float*)d_out, n);
    }
}

// round 7
// speedup vs baseline: 2.5651x; 1.0644x over previous
#include <cuda_runtime.h>

// ---- problem-size caps (ref: N=100000, E=1600000, G=512, F=128) ----
#define MAXN 131072
#define NSM  148

// scratch (no cudaMalloc allowed)
__device__ float  g_dot[MAXN];    // x@W per node
__device__ int    g_cnt[MAXN];    // in-degree count (deg = cnt + 1)
__device__ float  g_dis[MAXN];    // deg^-1/2 (for final output scaling)
__device__ float2 g_buf[4][MAXN]; // hop buffers: {t, s}; gather computes t*s

#if defined(__CUDA_ARCH__) && (__CUDA_ARCH__ >= 900)
#define GRID_DEP_SYNC() cudaGridDependencySynchronize()
#else
#define GRID_DEP_SYNC()
#endif

// ---------------------------------------------------------------------------
// Fused preamble, block-range specialized:
//   blocks [0, nGemv):      dot[i] = x[i,:] @ W      (DRAM streaming)
//   blocks [nGemv, grid):   cnt[col[e]] += 1         (random atomics)
// ---------------------------------------------------------------------------
__global__ void k_pre(const float* __restrict__ x, const float* __restrict__ W,
                      const int* __restrict__ col,
                      int n, int F, int E, int nGemv) {
    int lane = threadIdx.x & 31;
    if (blockIdx.x < nGemv) {
        int warp   = (blockIdx.x * blockDim.x + threadIdx.x) >> 5;
        int nwarps = (nGemv * blockDim.x) >> 5;
        if (F == 128) {
            float4 wv = *reinterpret_cast<const float4*>(W + lane * 4);
            for (int node = warp; node < n; node += nwarps) {
                float4 xv = *reinterpret_cast<const float4*>(x + (size_t)node * 128 + lane * 4);
                float acc = xv.x * wv.x + xv.y * wv.y + xv.z * wv.z + xv.w * wv.w;
                #pragma unroll
                for (int o = 16; o; o >>= 1) acc += __shfl_xor_sync(0xffffffffu, acc, o);
                if (lane == 0) g_dot[node] = acc;
            }
        } else {
            for (int node = warp; node < n; node += nwarps) {
                const float* xr = x + (size_t)node * F;
                float acc = 0.0f;
                for (int j = lane; j < F; j += 32) acc += xr[j] * W[j];
                #pragma unroll
                for (int o = 16; o; o >>= 1) acc += __shfl_xor_sync(0xffffffffu, acc, o);
                if (lane == 0) g_dot[node] = acc;
            }
        }
    } else {
        int tid = (blockIdx.x - nGemv) * blockDim.x + threadIdx.x;
        int nth = (gridDim.x - nGemv) * blockDim.x;
        int E4  = E >> 2;
        for (int q = tid; q < E4; q += nth) {
            int4 c = reinterpret_cast<const int4*>(col)[q];
            atomicAdd(&g_cnt[c.x], 1);
            atomicAdd(&g_cnt[c.y], 1);
            atomicAdd(&g_cnt[c.z], 1);
            atomicAdd(&g_cnt[c.w], 1);
        }
        if (tid == 0) for (int e = E4 << 2; e < E; e++) atomicAdd(&g_cnt[col[e]], 1);
    }
}

// Initialize all hop buffers in one pass:
//   B0 = {dot, dis}      (hop-0 gather yields dis*dot = u0)
//   B1 = B2 = {0, dinv}  (accumulators; s-field preloaded for next gather)
//   B3 = {0, 0}
//   g_dis saved for k_out
__global__ void k_scale(int n) {
    GRID_DEP_SYNC();
    int i = blockIdx.x * blockDim.x + threadIdx.x;
    if (i < n) {
        float deg  = (float)(g_cnt[i] + 1);   // +1 self-loop
        float dinv = __frcp_rn(deg);
        float dis  = rsqrtf(deg);
        g_dis[i]     = dis;
        g_buf[0][i]  = make_float2(g_dot[i], dis);
        g_buf[1][i]  = make_float2(0.0f, dinv);
        g_buf[2][i]  = make_float2(0.0f, dinv);
        g_buf[3][i]  = make_float2(0.0f, 0.0f);
    }
}

// One hop: dst.t[c] += src.t[r]*src.s[r] over all edges, plus self-loops.
template<int SRC>
__global__ void k_scatter(const int* __restrict__ row, const int* __restrict__ col,
                          int E, int n) {
    GRID_DEP_SYNC();
    const float2* __restrict__ src = g_buf[SRC];
    float2*       __restrict__ dst = g_buf[SRC + 1];
    int tid = blockIdx.x * blockDim.x + threadIdx.x;
    int nth = gridDim.x * blockDim.x;

    // self-loop term: dst.t[i] += src.t[i]*src.s[i] (coalesced)
    for (int i = tid; i < n; i += nth) {
        float2 v = src[i];
        atomicAdd(&dst[i].x, v.x * v.y);
    }

    int E4 = E >> 2;
    for (int q = tid; q < E4; q += nth) {
        int4 r = reinterpret_cast<const int4*>(row)[q];
        int4 c = reinterpret_cast<const int4*>(col)[q];
        float2 a0 = __ldg(&src[r.x]);
        float2 a1 = __ldg(&src[r.y]);
        float2 a2 = __ldg(&src[r.z]);
        float2 a3 = __ldg(&src[r.w]);
        atomicAdd(&dst[c.x].x, a0.x * a0.y);
        atomicAdd(&dst[c.y].x, a1.x * a1.y);
        atomicAdd(&dst[c.z].x, a2.x * a2.y);
        atomicAdd(&dst[c.w].x, a3.x * a3.y);
    }
    if (tid == 0) {
        for (int e = E4 << 2; e < E; e++) {
            float2 a = src[row[e]];
            atomicAdd(&dst[col[e]].x, a.x * a.y);
        }
    }
}

// fused scatter-mean + output: block g owns graph g (batch sorted).
__global__ void k_out(const int* __restrict__ batch, const float* __restrict__ bias,
                      float* __restrict__ out, int n) {
    GRID_DEP_SYNC();
    __shared__ int s_lo, s_hi;
    __shared__ float s_part[8];
    int g = blockIdx.x;

    if (threadIdx.x < 2) {
        int target = g + threadIdx.x;        // lower_bound(target)
        int lo = 0, hi = n;
        while (lo < hi) {
            int mid = (lo + hi) >> 1;
            if (batch[mid] < target) lo = mid + 1; else hi = mid;
        }
        if (threadIdx.x == 0) s_lo = lo; else s_hi = lo;
    }
    __syncthreads();

    int lo = s_lo, hi = s_hi;
    float local = 0.0f;
    for (int i = lo + threadIdx.x; i < hi; i += blockDim.x)
        local += g_dis[i] * g_buf[3][i].x;

    #pragma unroll
    for (int o = 16; o; o >>= 1) local += __shfl_xor_sync(0xffffffffu, local, o);
    int warp = threadIdx.x >> 5;
    if ((threadIdx.x & 31) == 0) s_part[warp] = local;
    __syncthreads();
    if (threadIdx.x == 0) {
        float sum = 0.0f;
        #pragma unroll
        for (int w = 0; w < 8; w++) sum += s_part[w];
        int c = hi - lo;
        out[g] = (c > 0) ? (sum / (float)c + bias[0]) : 0.0f;
    }
}

// ---------------------------------------------------------------------------
extern "C" void kernel_launch(void* const* d_in, const int* in_sizes, int n_in,
                              void* d_out, int out_size) {
    const float* x     = (const float*)d_in[0];   // [N, F]
    const float* W     = (const float*)d_in[1];   // [F, 1]
    const float* b     = (const float*)d_in[2];   // [1]
    const int*   ei    = (const int*)d_in[3];     // [2, E]
    const int*   batch = (const int*)d_in[4];     // [N]

    int F = in_sizes[1];
    int n = in_sizes[4];
    int E = in_sizes[3] / 2;
    int G = out_size;

    const int* row = ei;       // edge_index[0]
    const int* col = ei + E;   // edge_index[1]

    const int TB = 256;
    auto nbk = [](int v, int tb) { return (v + tb - 1) / tb; };

    // zero in-degree counters
    void* p_cnt;
    cudaGetSymbolAddress(&p_cnt, g_cnt);
    cudaMemsetAsync(p_cnt, 0, (size_t)n * sizeof(int));

    cudaLaunchAttribute pdlAttr[1];
    pdlAttr[0].id = cudaLaunchAttributeProgrammaticStreamSerialization;
    pdlAttr[0].val.programmaticStreamSerializationAllowed = 1;

    // --- preamble (predecessor is a memset: no PDL) ---
    int nGemv = NSM * 5;                 // 740 DRAM-streaming blocks
    int nDeg  = NSM * 3;                 // 444 random-atomic blocks
    k_pre<<<nGemv + nDeg, TB>>>(x, W, col, n, F, E, nGemv);

    // --- remaining kernels: PDL-chained ---
    {
        cudaLaunchConfig_t cfg = {};
        cfg.blockDim = dim3(TB, 1, 1);
        cfg.attrs = pdlAttr;
        cfg.numAttrs = 1;

        cfg.gridDim = dim3(nbk(n, TB), 1, 1);
        cudaLaunchKernelEx(&cfg, k_scale, n);

        const int scatGrid = NSM * 8;    // single wave @ 2048 thr/SM
        cfg.gridDim = dim3(scatGrid, 1, 1);
        cudaLaunchKernelEx(&cfg, k_scatter<0>, row, col, E, n);
        cudaLaunchKernelEx(&cfg, k_scatter<1>, row, col, E, n);
        cudaLaunchKernelEx(&cfg, k_scatter<2>, row, col, E, n);

        cfg.gridDim = dim3(G, 1, 1);
        cudaLaunchKernelEx(&cfg, k_out, batch, b, (float*)d_out, n);
    }
}

// round 8
// speedup vs baseline: 2.5944x; 1.0114x over previous
#include <cuda_runtime.h>

// ---- problem-size caps (ref: N=100000, E=1600000, G=512, F=128) ----
#define MAXN 131072
#define NSM  148

// scratch (no cudaMalloc allowed)
__device__ float  g_dot[MAXN];    // x@W per node
__device__ int    g_cnt[MAXN];    // in-degree count (deg = cnt + 1)
__device__ float  g_dis[MAXN];    // deg^-1/2 (for final output scaling)
__device__ float2 g_buf[4][MAXN]; // hop buffers: {t, s}; gather computes t*s

#if defined(__CUDA_ARCH__) && (__CUDA_ARCH__ >= 900)
#define GRID_DEP_SYNC() cudaGridDependencySynchronize()
#else
#define GRID_DEP_SYNC()
#endif

// ---------------------------------------------------------------------------
// Fused preamble, block-range specialized:
//   blocks [0, nGemv):      dot[i] = x[i,:] @ W      (DRAM streaming)
//   blocks [nGemv, grid):   cnt[col[e]] += 1         (random atomics)
// ---------------------------------------------------------------------------
__global__ void k_pre(const float* __restrict__ x, const float* __restrict__ W,
                      const int* __restrict__ col,
                      int n, int F, int E, int nGemv) {
    int lane = threadIdx.x & 31;
    if (blockIdx.x < nGemv) {
        int warp   = (blockIdx.x * blockDim.x + threadIdx.x) >> 5;
        int nwarps = (nGemv * blockDim.x) >> 5;
        if (F == 128) {
            float4 wv = *reinterpret_cast<const float4*>(W + lane * 4);
            for (int node = warp; node < n; node += nwarps) {
                float4 xv = *reinterpret_cast<const float4*>(x + (size_t)node * 128 + lane * 4);
                float acc = xv.x * wv.x + xv.y * wv.y + xv.z * wv.z + xv.w * wv.w;
                #pragma unroll
                for (int o = 16; o; o >>= 1) acc += __shfl_xor_sync(0xffffffffu, acc, o);
                if (lane == 0) g_dot[node] = acc;
            }
        } else {
            for (int node = warp; node < n; node += nwarps) {
                const float* xr = x + (size_t)node * F;
                float acc = 0.0f;
                for (int j = lane; j < F; j += 32) acc += xr[j] * W[j];
                #pragma unroll
                for (int o = 16; o; o >>= 1) acc += __shfl_xor_sync(0xffffffffu, acc, o);
                if (lane == 0) g_dot[node] = acc;
            }
        }
    } else {
        int tid = (blockIdx.x - nGemv) * blockDim.x + threadIdx.x;
        int nth = (gridDim.x - nGemv) * blockDim.x;
        int E4  = E >> 2;
        for (int q = tid; q < E4; q += nth) {
            int4 c = reinterpret_cast<const int4*>(col)[q];
            atomicAdd(&g_cnt[c.x], 1);
            atomicAdd(&g_cnt[c.y], 1);
            atomicAdd(&g_cnt[c.z], 1);
            atomicAdd(&g_cnt[c.w], 1);
        }
        if (tid == 0) for (int e = E4 << 2; e < E; e++) atomicAdd(&g_cnt[col[e]], 1);
    }
}

// Initialize all hop buffers in one pass:
//   B0 = {dot, dis}; B1 = B2 = {0, dinv}; B3 = {0, 0}; save dis.
__global__ void k_scale(int n) {
    GRID_DEP_SYNC();
    int i = blockIdx.x * blockDim.x + threadIdx.x;
    if (i < n) {
        float deg  = (float)(g_cnt[i] + 1);   // +1 self-loop
        float dinv = __frcp_rn(deg);
        float dis  = rsqrtf(deg);
        g_dis[i]     = dis;
        g_buf[0][i]  = make_float2(g_dot[i], dis);
        g_buf[1][i]  = make_float2(0.0f, dinv);
        g_buf[2][i]  = make_float2(0.0f, dinv);
        g_buf[3][i]  = make_float2(0.0f, 0.0f);
    }
}

// One hop: dst.t[c] += src.t[r]*src.s[r] over all edges, plus self-loops.
// 8 edges per iteration for high per-warp MLP.
template<int SRC>
__global__ void __launch_bounds__(256, 6)
k_scatter(const int* __restrict__ row, const int* __restrict__ col, int E, int n) {
    GRID_DEP_SYNC();
    const float2* __restrict__ src = g_buf[SRC];
    float2*       __restrict__ dst = g_buf[SRC + 1];
    int tid = blockIdx.x * blockDim.x + threadIdx.x;
    int nth = gridDim.x * blockDim.x;

    int E8 = E >> 3;
    for (int q = tid; q < E8; q += nth) {
        int4 r0 = reinterpret_cast<const int4*>(row)[q * 2];
        int4 r1 = reinterpret_cast<const int4*>(row)[q * 2 + 1];
        int4 c0 = reinterpret_cast<const int4*>(col)[q * 2];
        int4 c1 = reinterpret_cast<const int4*>(col)[q * 2 + 1];
        // 8 independent gathers in flight
        float2 a0 = __ldg(&src[r0.x]);
        float2 a1 = __ldg(&src[r0.y]);
        float2 a2 = __ldg(&src[r0.z]);
        float2 a3 = __ldg(&src[r0.w]);
        float2 a4 = __ldg(&src[r1.x]);
        float2 a5 = __ldg(&src[r1.y]);
        float2 a6 = __ldg(&src[r1.z]);
        float2 a7 = __ldg(&src[r1.w]);
        atomicAdd(&dst[c0.x].x, a0.x * a0.y);
        atomicAdd(&dst[c0.y].x, a1.x * a1.y);
        atomicAdd(&dst[c0.z].x, a2.x * a2.y);
        atomicAdd(&dst[c0.w].x, a3.x * a3.y);
        atomicAdd(&dst[c1.x].x, a4.x * a4.y);
        atomicAdd(&dst[c1.y].x, a5.x * a5.y);
        atomicAdd(&dst[c1.z].x, a6.x * a6.y);
        atomicAdd(&dst[c1.w].x, a7.x * a7.y);
    }
    // self-loop term: dst.t[i] += src.t[i]*src.s[i] (coalesced)
    for (int i = tid; i < n; i += nth) {
        float2 v = src[i];
        atomicAdd(&dst[i].x, v.x * v.y);
    }
    if (tid == 0) {
        for (int e = E8 << 3; e < E; e++) {
            float2 a = src[row[e]];
            atomicAdd(&dst[col[e]].x, a.x * a.y);
        }
    }
}

// fused scatter-mean + output: block g owns graph g (batch sorted).
__global__ void k_out(const int* __restrict__ batch, const float* __restrict__ bias,
                      float* __restrict__ out, int n) {
    GRID_DEP_SYNC();
    __shared__ int s_lo, s_hi;
    __shared__ float s_part[8];
    int g = blockIdx.x;

    if (threadIdx.x < 2) {
        int target = g + threadIdx.x;        // lower_bound(target)
        int lo = 0, hi = n;
        while (lo < hi) {
            int mid = (lo + hi) >> 1;
            if (batch[mid] < target) lo = mid + 1; else hi = mid;
        }
        if (threadIdx.x == 0) s_lo = lo; else s_hi = lo;
    }
    __syncthreads();

    int lo = s_lo, hi = s_hi;
    float local = 0.0f;
    for (int i = lo + threadIdx.x; i < hi; i += blockDim.x)
        local += g_dis[i] * g_buf[3][i].x;

    #pragma unroll
    for (int o = 16; o; o >>= 1) local += __shfl_xor_sync(0xffffffffu, local, o);
    int warp = threadIdx.x >> 5;
    if ((threadIdx.x & 31) == 0) s_part[warp] = local;
    __syncthreads();
    if (threadIdx.x == 0) {
        float sum = 0.0f;
        #pragma unroll
        for (int w = 0; w < 8; w++) sum += s_part[w];
        int c = hi - lo;
        out[g] = (c > 0) ? (sum / (float)c + bias[0]) : 0.0f;
    }
}

// ---------------------------------------------------------------------------
extern "C" void kernel_launch(void* const* d_in, const int* in_sizes, int n_in,
                              void* d_out, int out_size) {
    const float* x     = (const float*)d_in[0];   // [N, F]
    const float* W     = (const float*)d_in[1];   // [F, 1]
    const float* b     = (const float*)d_in[2];   // [1]
    const int*   ei    = (const int*)d_in[3];     // [2, E]
    const int*   batch = (const int*)d_in[4];     // [N]

    int F = in_sizes[1];
    int n = in_sizes[4];
    int E = in_sizes[3] / 2;
    int G = out_size;

    const int* row = ei;       // edge_index[0]
    const int* col = ei + E;   // edge_index[1]

    const int TB = 256;
    auto nbk = [](int v, int tb) { return (v + tb - 1) / tb; };

    // zero in-degree counters
    void* p_cnt;
    cudaGetSymbolAddress(&p_cnt, g_cnt);
    cudaMemsetAsync(p_cnt, 0, (size_t)n * sizeof(int));

    cudaLaunchAttribute pdlAttr[1];
    pdlAttr[0].id = cudaLaunchAttributeProgrammaticStreamSerialization;
    pdlAttr[0].val.programmaticStreamSerializationAllowed = 1;

    // --- preamble (predecessor is a memset: no PDL) ---
    int nGemv = NSM * 4;                 // DRAM-streaming GEMV blocks
    int nDeg  = NSM * 4;                 // random-atomic degree blocks
    k_pre<<<nGemv + nDeg, TB>>>(x, W, col, n, F, E, nGemv);

    // --- remaining kernels: PDL-chained ---
    {
        cudaLaunchConfig_t cfg = {};
        cfg.blockDim = dim3(TB, 1, 1);
        cfg.attrs = pdlAttr;
        cfg.numAttrs = 1;

        cfg.gridDim = dim3(nbk(n, TB), 1, 1);
        cudaLaunchKernelEx(&cfg, k_scale, n);

        const int scatGrid = NSM * 6;    // single wave @ 6 blocks/SM (regs ~40)
        cfg.gridDim = dim3(scatGrid, 1, 1);
        cudaLaunchKernelEx(&cfg, k_scatter<0>, row, col, E, n);
        cudaLaunchKernelEx(&cfg, k_scatter<1>, row, col, E, n);
        cudaLaunchKernelEx(&cfg, k_scatter<2>, row, col, E, n);

        cfg.gridDim = dim3(G, 1, 1);
        cudaLaunchKernelEx(&cfg, k_out, batch, b, (float*)d_out, n);
    }
}